// round 2
// baseline (speedup 1.0000x reference)
#include <cuda_runtime.h>

typedef unsigned long long u64;

// ---- packed f32x2 helpers (sm_103a) ----
__device__ __forceinline__ u64 pack2(float lo, float hi) {
    u64 r; asm("mov.b64 %0, {%1, %2};" : "=l"(r) : "f"(lo), "f"(hi)); return r;
}
__device__ __forceinline__ void unpack2(u64 v, float& lo, float& hi) {
    asm("mov.b64 {%0, %1}, %2;" : "=f"(lo), "=f"(hi) : "l"(v));
}
__device__ __forceinline__ u64 fma2(u64 a, u64 b, u64 c) {
    u64 d; asm("fma.rn.f32x2 %0, %1, %2, %3;" : "=l"(d) : "l"(a), "l"(b), "l"(c));
    return d;
}

#define TPB 256
#define PPT 4                 // points per thread
#define MAX_PAL 1024          // palette capacity in shared (actual M = 128)

// Fixed-point accumulator: integer atomics commute exactly -> deterministic.
#define SUM_SCALE 4294967296.0   // 2^32

__device__ unsigned long long g_sum = 0ULL;
__device__ unsigned int g_count = 0u;

// Per palette entry j (splatted pairs):
//   s_a[j] = { pack2(px,px), pack2(py,py) }
//   s_b[j] = { pack2(pz,pz), pack2(c,c) },  c = 0.5*(px^2+py^2+pz^2)
// score = c - x*px - y*py - z*pz;  d = sqrt(max(|x|^2 + 2*min_score, 0))

__global__ void __launch_bounds__(TPB)
ncd_fused(const float* __restrict__ pts, const float* __restrict__ pal,
          float* __restrict__ out, int N, int M)
{
    __shared__ ulonglong2 s_a[MAX_PAL];
    __shared__ ulonglong2 s_b[MAX_PAL];
    __shared__ float s_warp[TPB / 32];
    __shared__ bool s_last;

    const int tid = threadIdx.x;

    for (int j = tid; j < M; j += TPB) {
        float px = pal[3 * j + 0];
        float py = pal[3 * j + 1];
        float pz = pal[3 * j + 2];
        float c  = 0.5f * (px * px + py * py + pz * pz);
        s_a[j] = make_ulonglong2(pack2(px, px), pack2(py, py));
        s_b[j] = make_ulonglong2(pack2(pz, pz), pack2(c, c));
    }
    __syncthreads();

    float tsum = 0.0f;
    const long long stride = (long long)gridDim.x * TPB * PPT;

    for (long long base = ((long long)blockIdx.x * TPB + tid) * PPT;
         base < N; base += stride)
    {
        float x0, y0, z0, x1, y1, z1, x2, y2, z2, x3, y3, z3;
        bool v1, v2, v3;

        if (base + PPT <= (long long)N) {
            // vector path: 12 consecutive floats, 16B-aligned (base % 4 == 0)
            const float4* p4 = (const float4*)(pts + base * 3);
            float4 f0 = p4[0], f1 = p4[1], f2 = p4[2];
            x0 = f0.x; y0 = f0.y; z0 = f0.z;
            x1 = f0.w; y1 = f1.x; z1 = f1.y;
            x2 = f1.z; y2 = f1.w; z2 = f2.x;
            x3 = f2.y; y3 = f2.z; z3 = f2.w;
            v1 = v2 = v3 = true;
        } else {
            x0 = pts[base * 3 + 0]; y0 = pts[base * 3 + 1]; z0 = pts[base * 3 + 2];
            v1 = (base + 1 < (long long)N);
            v2 = (base + 2 < (long long)N);
            v3 = (base + 3 < (long long)N);
            x1 = v1 ? pts[base * 3 + 3]  : 0.0f;
            y1 = v1 ? pts[base * 3 + 4]  : 0.0f;
            z1 = v1 ? pts[base * 3 + 5]  : 0.0f;
            x2 = v2 ? pts[base * 3 + 6]  : 0.0f;
            y2 = v2 ? pts[base * 3 + 7]  : 0.0f;
            z2 = v2 ? pts[base * 3 + 8]  : 0.0f;
            x3 = v3 ? pts[base * 3 + 9]  : 0.0f;
            y3 = v3 ? pts[base * 3 + 10] : 0.0f;
            z3 = v3 ? pts[base * 3 + 11] : 0.0f;
        }

        const u64 nxA = pack2(-x0, -x1), nyA = pack2(-y0, -y1), nzA = pack2(-z0, -z1);
        const u64 nxB = pack2(-x2, -x3), nyB = pack2(-y2, -y3), nzB = pack2(-z2, -z3);
        const float n0 = __fmaf_rn(x0, x0, __fmaf_rn(y0, y0, z0 * z0));
        const float n1 = __fmaf_rn(x1, x1, __fmaf_rn(y1, y1, z1 * z1));
        const float n2 = __fmaf_rn(x2, x2, __fmaf_rn(y2, y2, z2 * z2));
        const float n3 = __fmaf_rn(x3, x3, __fmaf_rn(y3, y3, z3 * z3));

        float m0 = 1e30f, m1 = 1e30f, m2 = 1e30f, m3 = 1e30f;

        #pragma unroll 4
        for (int j = 0; j < M; j++) {
            const ulonglong2 a = s_a[j];
            const ulonglong2 b = s_b[j];
            const u64 inner = fma2(nzA, b.x, b.y);           // shared z? no: A-only
            const u64 scA = fma2(nxA, a.x, fma2(nyA, a.y, inner));
            const u64 scB = fma2(nxB, a.x, fma2(nyB, a.y, fma2(nzB, b.x, b.y)));
            float lo, hi;
            unpack2(scA, lo, hi);
            m0 = fminf(m0, lo); m1 = fminf(m1, hi);
            unpack2(scB, lo, hi);
            m2 = fminf(m2, lo); m3 = fminf(m3, hi);
        }

        tsum += sqrtf(fmaxf(__fmaf_rn(2.0f, m0, n0), 0.0f));
        if (v1) tsum += sqrtf(fmaxf(__fmaf_rn(2.0f, m1, n1), 0.0f));
        if (v2) tsum += sqrtf(fmaxf(__fmaf_rn(2.0f, m2, n2), 0.0f));
        if (v3) tsum += sqrtf(fmaxf(__fmaf_rn(2.0f, m3, n3), 0.0f));
    }

    // ---- block reduction (deterministic order within block) ----
    #pragma unroll
    for (int o = 16; o; o >>= 1) tsum += __shfl_down_sync(0xFFFFFFFFu, tsum, o);
    if ((tid & 31) == 0) s_warp[tid >> 5] = tsum;
    __syncthreads();

    if (tid == 0) {
        float partial = 0.0f;
        #pragma unroll
        for (int w = 0; w < TPB / 32; w++) partial += s_warp[w];
        // fixed-point accumulate: exact integer adds -> order-independent
        unsigned long long q = (unsigned long long)((double)partial * SUM_SCALE);
        atomicAdd(&g_sum, q);
        __threadfence();
        unsigned int prev = atomicAdd(&g_count, 1u);
        s_last = (prev == gridDim.x - 1);
    }
    __syncthreads();

    if (s_last && tid == 0) {
        __threadfence();
        unsigned long long total = atomicAdd(&g_sum, 0ULL);
        out[0] = (float)(((double)total / SUM_SCALE) / (double)N);
        // reset for next graph replay
        g_sum = 0ULL;
        g_count = 0u;
    }
}

extern "C" void kernel_launch(void* const* d_in, const int* in_sizes, int n_in,
                              void* d_out, int out_size)
{
    const float* pts = (const float*)d_in[0];   // output_colors (N,3)
    const float* pal = (const float*)d_in[1];   // target_palette (M,3)
    float* out = (float*)d_out;

    const int N = in_sizes[0] / 3;
    int M = in_sizes[1] / 3;
    if (M > MAX_PAL) M = MAX_PAL;  // dataset has M=128

    long long blocks_ll = ((long long)N + (long long)TPB * PPT - 1) / ((long long)TPB * PPT);
    int blocks = (int)(blocks_ll > 1024 ? 1024 : blocks_ll);
    if (blocks < 1) blocks = 1;

    ncd_fused<<<blocks, TPB>>>(pts, pal, out, N, M);
}

// round 3
// speedup vs baseline: 1.2064x; 1.2064x over previous
#include <cuda_runtime.h>

typedef unsigned long long u64;

// ---- packed f32x2 helpers (sm_103a) ----
__device__ __forceinline__ u64 pack2(float lo, float hi) {
    u64 r; asm("mov.b64 %0, {%1, %2};" : "=l"(r) : "f"(lo), "f"(hi)); return r;
}
__device__ __forceinline__ void unpack2(u64 v, float& lo, float& hi) {
    asm("mov.b64 {%0, %1}, %2;" : "=f"(lo), "=f"(hi) : "l"(v));
}
__device__ __forceinline__ u64 fma2(u64 a, u64 b, u64 c) {
    u64 d; asm("fma.rn.f32x2 %0, %1, %2, %3;" : "=l"(d) : "l"(a), "l"(b), "l"(c));
    return d;
}

#define TPB 128
#define PPT 2                  // points per thread
#define MAX_PAIRS 512          // palette-pair capacity (M up to 1024)

// Fixed-point accumulator: integer atomics commute exactly -> deterministic.
#define SUM_SCALE 4294967296.0 // 2^32

__device__ unsigned long long g_sum = 0ULL;
__device__ unsigned int g_count = 0u;

// Palette stored as PAIRS of entries packed in f32x2 lanes:
//   s_xy[k] = { pack2(px_{2k}, px_{2k+1}), pack2(py_{2k}, py_{2k+1}) }
//   s_zc[k] = { pack2(pz_{2k}, pz_{2k+1}), pack2(c_{2k},  c_{2k+1}) }
// with c = 0.5*(px^2+py^2+pz^2).
// Per point, splat (-x,-x), (-y,-y), (-z,-z) once; then per pair k:
//   score2 = fma2(sx, xx, fma2(sy, yy, fma2(sz, zz, cc)))
// gives scores of entries 2k and 2k+1 simultaneously.
// d = sqrt(max(|x|^2 + 2*min_score, 0)).

__global__ void __launch_bounds__(TPB)
ncd_fused(const float* __restrict__ pts, const float* __restrict__ pal,
          float* __restrict__ out, int N, int M)
{
    __shared__ ulonglong2 s_xy[MAX_PAIRS];
    __shared__ ulonglong2 s_zc[MAX_PAIRS];
    __shared__ float s_warp[TPB / 32];
    __shared__ bool s_last;

    const int tid = threadIdx.x;
    const int npair = (M + 1) >> 1;

    // Build packed palette pairs in shared.
    for (int k = tid; k < npair; k += TPB) {
        const int j0 = 2 * k;
        const int j1 = (2 * k + 1 < M) ? (2 * k + 1) : j0;  // dup tail if M odd
        const float px0 = pal[3 * j0 + 0], py0 = pal[3 * j0 + 1], pz0 = pal[3 * j0 + 2];
        const float px1 = pal[3 * j1 + 0], py1 = pal[3 * j1 + 1], pz1 = pal[3 * j1 + 2];
        const float c0 = 0.5f * (px0 * px0 + py0 * py0 + pz0 * pz0);
        const float c1 = 0.5f * (px1 * px1 + py1 * py1 + pz1 * pz1);
        s_xy[k] = make_ulonglong2(pack2(px0, px1), pack2(py0, py1));
        s_zc[k] = make_ulonglong2(pack2(pz0, pz1), pack2(c0, c1));
    }
    __syncthreads();

    float tsum = 0.0f;
    const long long stride = (long long)gridDim.x * TPB * PPT;

    for (long long base = ((long long)blockIdx.x * TPB + tid) * PPT;
         base < N; base += stride)
    {
        const bool v1 = (base + 1 < (long long)N);

        // Load 2 points (6 floats, float2-aligned).
        const float2* p2 = (const float2*)(pts + base * 3);
        float x0, y0, z0, x1, y1, z1;
        {
            const float2 f0 = p2[0];
            x0 = f0.x; y0 = f0.y;
            if (v1) {
                const float2 f1 = p2[1];
                const float2 f2 = p2[2];
                z0 = f1.x;
                x1 = f1.y; y1 = f2.x; z1 = f2.y;
            } else {
                z0 = pts[base * 3 + 2];
                x1 = x0; y1 = y0; z1 = z0;
            }
        }

        // Point splats (registers, once per point).
        const u64 sx0 = pack2(-x0, -x0), sy0 = pack2(-y0, -y0), sz0 = pack2(-z0, -z0);
        const u64 sx1 = pack2(-x1, -x1), sy1 = pack2(-y1, -y1), sz1 = pack2(-z1, -z1);
        const float n0 = __fmaf_rn(x0, x0, __fmaf_rn(y0, y0, z0 * z0));
        const float n1 = __fmaf_rn(x1, x1, __fmaf_rn(y1, y1, z1 * z1));

        float m0 = 1e30f, m1 = 1e30f;

        #pragma unroll 4
        for (int k = 0; k < npair; k++) {
            const ulonglong2 a = s_xy[k];   // xx, yy
            const ulonglong2 b = s_zc[k];   // zz, cc
            const u64 s0 = fma2(sx0, a.x, fma2(sy0, a.y, fma2(sz0, b.x, b.y)));
            const u64 s1 = fma2(sx1, a.x, fma2(sy1, a.y, fma2(sz1, b.x, b.y)));
            float lo, hi;
            unpack2(s0, lo, hi);
            m0 = fminf(m0, fminf(lo, hi));
            unpack2(s1, lo, hi);
            m1 = fminf(m1, fminf(lo, hi));
        }

        tsum += sqrtf(fmaxf(__fmaf_rn(2.0f, m0, n0), 0.0f));
        if (v1) tsum += sqrtf(fmaxf(__fmaf_rn(2.0f, m1, n1), 0.0f));
    }

    // ---- block reduction (deterministic order within block) ----
    #pragma unroll
    for (int o = 16; o; o >>= 1) tsum += __shfl_down_sync(0xFFFFFFFFu, tsum, o);
    if ((tid & 31) == 0) s_warp[tid >> 5] = tsum;
    __syncthreads();

    if (tid == 0) {
        float partial = 0.0f;
        #pragma unroll
        for (int w = 0; w < TPB / 32; w++) partial += s_warp[w];
        // fixed-point accumulate: exact integer adds -> order-independent
        const unsigned long long q = (unsigned long long)((double)partial * SUM_SCALE);
        atomicAdd(&g_sum, q);
        __threadfence();
        const unsigned int prev = atomicAdd(&g_count, 1u);
        s_last = (prev == gridDim.x - 1);
    }
    __syncthreads();

    if (s_last && tid == 0) {
        __threadfence();
        const unsigned long long total = atomicAdd(&g_sum, 0ULL);
        out[0] = (float)(((double)total / SUM_SCALE) / (double)N);
        // reset for next graph replay
        g_sum = 0ULL;
        g_count = 0u;
    }
}

extern "C" void kernel_launch(void* const* d_in, const int* in_sizes, int n_in,
                              void* d_out, int out_size)
{
    const float* pts = (const float*)d_in[0];   // output_colors (N,3)
    const float* pal = (const float*)d_in[1];   // target_palette (M,3)
    float* out = (float*)d_out;

    const int N = in_sizes[0] / 3;
    int M = in_sizes[1] / 3;
    if (M > 2 * MAX_PAIRS) M = 2 * MAX_PAIRS;   // dataset has M=128

    long long blocks_ll = ((long long)N + (long long)TPB * PPT - 1) / ((long long)TPB * PPT);
    if (blocks_ll < 1) blocks_ll = 1;
    if (blocks_ll > 65535) blocks_ll = 65535;
    const int blocks = (int)blocks_ll;          // N=131072 -> 512 blocks

    ncd_fused<<<blocks, TPB>>>(pts, pal, out, N, M);
}